// round 11
// baseline (speedup 1.0000x reference)
#include <cuda_runtime.h>
#include <cuda_bf16.h>

#define HW    128
#define IMG   (HW*HW)
#define BATCH 64

// Scratch buffers (allocation-free rule: __device__ globals)
__device__ float g_bufA[(size_t)BATCH * 22 * IMG];  // 22-ch concat; x lives in ch 12..21
__device__ float g_bufB[(size_t)BATCH * 24 * IMG];
__device__ float g_bufC[(size_t)BATCH * 24 * IMG];

// ---------------------------------------------------------------------------
// bf16 split helpers: f = hi + lo with hi = bf16_rn(f), lo = bf16_rn(f - hi).
// Products hi*hi, hi*lo, lo*hi in bf16 MMA w/ fp32 accum give ~1e-6 rel err.
// ---------------------------------------------------------------------------
__device__ __forceinline__ void split2(float f0, float f1, unsigned& hi, unsigned& lo) {
    __nv_bfloat16 h0 = __float2bfloat16(f0);
    __nv_bfloat16 h1 = __float2bfloat16(f1);
    __nv_bfloat16 l0 = __float2bfloat16(f0 - __bfloat162float(h0));
    __nv_bfloat16 l1 = __float2bfloat16(f1 - __bfloat162float(h1));
    hi = ((unsigned)__bfloat16_as_ushort(h1) << 16) | (unsigned)__bfloat16_as_ushort(h0);
    lo = ((unsigned)__bfloat16_as_ushort(l1) << 16) | (unsigned)__bfloat16_as_ushort(l0);
}

// mma.sync m16n8k8 bf16: C[16x8,f32] += A[16x8,bf16] * B[8x8,bf16]
__device__ __forceinline__ void mma_bf16(float c[4], unsigned a0, unsigned a1, unsigned b0) {
    asm("mma.sync.aligned.m16n8k8.row.col.f32.bf16.bf16.f32 "
        "{%0,%1,%2,%3}, {%4,%5}, {%6}, {%0,%1,%2,%3};"
        : "+f"(c[0]), "+f"(c[1]), "+f"(c[2]), "+f"(c[3])
        : "r"(a0), "r"(a1), "r"(b0));
}

// ---------------------------------------------------------------------------
// Per-sample 3x3 conv + eval-BN + ReLU via split-bf16 tensor-core MMA.
// CTA: 256 threads (8 warps), pixel tile 64x8 (halo 66x10).
// n-block-INNER warp-tile: per k-iter load A frags ONCE (8 LDS.32), then for
// each of NBK n-blocks load 2 B-frag words + issue 6 MMAs. A traffic no
// longer scales with NBK -> tensor pipe becomes the binding resource.
// ---------------------------------------------------------------------------
template<int CIN, int CINP, int COUT, int COUTP>
__global__ __launch_bounds__(256, 2)
void conv3x3_mma(const float* __restrict__ in, int in_nch,
                 const float* __restrict__ wflat, int wP, int wbase,
                 const float* __restrict__ gam, const float* __restrict__ bet,
                 const float* __restrict__ mea, const float* __restrict__ varr,
                 int bnoff,
                 float* __restrict__ out, int out_nch)
{
    constexpr int KC   = CINP / 8;           // k-chunks of 8 channels
    constexpr int NBK  = COUTP / 8;          // n-blocks of 8 outputs
    constexpr int RSW  = (CINP == 16) ? 20 : 28;  // record stride (words)
    constexpr int CHW  = CINP / 2;           // lo-section word offset
    constexpr int TXW  = 66, TYH = 10;       // halo tile
    constexpr int NREC = TXW * TYH;          // 660 pixel records
    constexpr int BSL  = 9 * KC * 32;        // B slots per n-block

    extern __shared__ unsigned sm[];
    unsigned* s_a  = sm;                     // NREC * RSW
    unsigned* s_bh = s_a + NREC * RSW;       // NBK * BSL
    unsigned* s_bl = s_bh + NBK * BSL;       // NBK * BSL
    float*    s_sc = (float*)(s_bl + NBK * BSL);
    float*    s_bi = s_sc + COUTP;

    const int tid = threadIdx.x;
    const int bS  = blockIdx.z;
    const int gx0 = blockIdx.x * 64;
    const int gy0 = blockIdx.y * 8;

    // ---- stage A: float -> (hi,lo) bf16 pair records ----
    const float* inb = in + (size_t)bS * in_nch * IMG;
    for (int u = tid; u < (CINP / 2) * NREC; u += 256) {
        int x  = u % TXW;
        int r  = u / TXW;
        int y  = r % TYH;
        int cp = r / TYH;                    // channel pair
        int gy = gy0 - 1 + y, gx = gx0 - 1 + x;
        float f0 = 0.f, f1 = 0.f;
        bool inimg = ((unsigned)gy < HW) && ((unsigned)gx < HW);
        if (inimg && 2 * cp < CIN)     f0 = inb[(size_t)(2 * cp) * IMG + gy * HW + gx];
        if (inimg && 2 * cp + 1 < CIN) f1 = inb[(size_t)(2 * cp + 1) * IMG + gy * HW + gx];
        unsigned hi, lo; split2(f0, f1, hi, lo);
        int rec = y * TXW + x;
        s_a[rec * RSW + cp]       = hi;
        s_a[rec * RSW + CHW + cp] = lo;
    }

    // ---- prep B: gmem weights -> fragment-ordered smem (hi/lo) ----
    const float* wsrc = wflat + (size_t)bS * wP + wbase;
    for (int s = tid; s < NBK * BSL; s += 256) {
        int lane = s & 31;
        int r = s >> 5;
        int kc = r % KC;  r /= KC;
        int sh = r % 9;   r /= 9;
        int nb = r;
        int o  = nb * 8 + (lane >> 2);       // n = g
        int i0 = kc * 8 + (lane & 3) * 2;    // k = 2t, 2t+1
        float w0 = (o < COUT && i0     < CIN) ? wsrc[(o * CIN + i0    ) * 9 + sh] : 0.f;
        float w1 = (o < COUT && i0 + 1 < CIN) ? wsrc[(o * CIN + i0 + 1) * 9 + sh] : 0.f;
        unsigned hi, lo; split2(w0, w1, hi, lo);
        s_bh[s] = hi;
        s_bl[s] = lo;
    }
    if (tid < COUTP) {
        float sc = 0.f, bi = 0.f;
        if (tid < COUT) {
            int c = bnoff + tid;
            float inv = gam[c] * rsqrtf(varr[c] + 1e-5f);
            sc = inv; bi = bet[c] - mea[c] * inv;
        }
        s_sc[tid] = sc; s_bi[tid] = bi;
    }
    __syncthreads();

    const int lane = tid & 31, warp = tid >> 5;
    const int g = lane >> 2, t = lane & 3;

    const unsigned* pbh = s_bh + lane;       // + nb*BSL + q*32 (immediates)
    const unsigned* pbl = s_bl + lane;
    float* ob = out + (size_t)bS * out_nch * IMG;

    // 16 m-pairs / 8 warps -> 2 warp-tiles per warp; all n-blocks per tile
    #pragma unroll 1
    for (int jj = 0; jj < 2; jj++) {
        const int mp = warp + 8 * jj;

        float acc[2][NBK][3][4];             // [m-block][n-block][split-term]
        #pragma unroll
        for (int m = 0; m < 2; m++)
            #pragma unroll
            for (int nb = 0; nb < NBK; nb++)
                #pragma unroll
                for (int e = 0; e < 3; e++)
                    #pragma unroll
                    for (int i = 0; i < 4; i++) acc[m][nb][e][i] = 0.f;

        const int mb0 = mp * 2, mb1 = mp * 2 + 1;
        const int base0 = ((mb0 >> 2) * TXW + (mb0 & 3) * 16 + g) * RSW + t;
        const int base1 = ((mb1 >> 2) * TXW + (mb1 & 3) * 16 + g) * RSW + t;

        #pragma unroll
        for (int ky = 0; ky < 3; ky++)
            #pragma unroll
            for (int kx = 0; kx < 3; kx++)
                #pragma unroll
                for (int kc = 0; kc < KC; kc++) {
                    const int q   = (ky * 3 + kx) * KC + kc;
                    const int off = (ky * TXW + kx) * RSW + kc * 4;
                    // A fragments: loaded ONCE, reused by all n-blocks
                    const unsigned ah0 = s_a[base0 + off];
                    const unsigned ah1 = s_a[base0 + off + 8 * RSW];
                    const unsigned al0 = s_a[base0 + off + CHW];
                    const unsigned al1 = s_a[base0 + off + CHW + 8 * RSW];
                    const unsigned ch0 = s_a[base1 + off];
                    const unsigned ch1 = s_a[base1 + off + 8 * RSW];
                    const unsigned cl0 = s_a[base1 + off + CHW];
                    const unsigned cl1 = s_a[base1 + off + CHW + 8 * RSW];
                    #pragma unroll
                    for (int nb = 0; nb < NBK; nb++) {
                        const unsigned b_h = pbh[nb * BSL + q * 32];
                        const unsigned b_l = pbl[nb * BSL + q * 32];
                        mma_bf16(acc[0][nb][0], ah0, ah1, b_h);
                        mma_bf16(acc[0][nb][1], ah0, ah1, b_l);
                        mma_bf16(acc[0][nb][2], al0, al1, b_h);
                        mma_bf16(acc[1][nb][0], ch0, ch1, b_h);
                        mma_bf16(acc[1][nb][1], ch0, ch1, b_l);
                        mma_bf16(acc[1][nb][2], cl0, cl1, b_h);
                    }
                }

        // ---- epilogue: combine split terms, BN + ReLU, store ----
        #pragma unroll
        for (int nb = 0; nb < NBK; nb++) {
            const int o0 = nb * 8 + 2 * t, o1 = o0 + 1;
            const float sc0 = s_sc[o0], bi0 = s_bi[o0];
            const float sc1 = s_sc[o1], bi1 = s_bi[o1];
            #pragma unroll
            for (int m = 0; m < 2; m++) {
                const int mb = mp * 2 + m;
                const int y  = gy0 + (mb >> 2);
                const int x  = gx0 + (mb & 3) * 16 + g;
                float c0 = acc[m][nb][0][0] + acc[m][nb][1][0] + acc[m][nb][2][0];
                float c1 = acc[m][nb][0][1] + acc[m][nb][1][1] + acc[m][nb][2][1];
                float c2 = acc[m][nb][0][2] + acc[m][nb][1][2] + acc[m][nb][2][2];
                float c3 = acc[m][nb][0][3] + acc[m][nb][1][3] + acc[m][nb][2][3];
                float* p = ob + (size_t)y * HW + x;
                if (o0 < COUT) {
                    p[(size_t)o0 * IMG]     = fmaxf(fmaf(c0, sc0, bi0), 0.f);
                    p[(size_t)o0 * IMG + 8] = fmaxf(fmaf(c2, sc0, bi0), 0.f);
                }
                if (o1 < COUT) {
                    p[(size_t)o1 * IMG]     = fmaxf(fmaf(c1, sc1, bi1), 0.f);
                    p[(size_t)o1 * IMG + 8] = fmaxf(fmaf(c3, sc1, bi1), 0.f);
                }
            }
        }
    }
}

// ---------------------------------------------------------------------------
// Copy x into channels 12..21 of bufA (makes the dense-skip concat free).
// ---------------------------------------------------------------------------
__global__ void copy_x_kernel(const float* __restrict__ x, float* __restrict__ bufA)
{
    size_t idx = (size_t)blockIdx.x * blockDim.x + threadIdx.x;
    const size_t total = (size_t)BATCH * 10 * IMG;
    if (idx < total) {
        int p = (int)(idx % IMG);
        int c = (int)((idx / IMG) % 10);
        int b = (int)(idx / ((size_t)IMG * 10));
        bufA[((size_t)b * 22 + 12 + c) * IMG + p] = x[idx];
    }
}

// ---------------------------------------------------------------------------
// Final per-sample 1x1 conv: [B,22,H,W] x [B,11,22] -> [B,11,H,W]
// ---------------------------------------------------------------------------
__global__ __launch_bounds__(256)
void conv1x1_kernel(const float* __restrict__ in, const float* __restrict__ w4,
                    float* __restrict__ out)
{
    __shared__ float s_w[11 * 22];
    const int b   = blockIdx.y;
    const int tid = threadIdx.x;
    if (tid < 242) s_w[tid] = w4[b * 242 + tid];
    __syncthreads();

    const int p0 = blockIdx.x * (256 * 4) + tid;
    const float* inb = in  + (size_t)b * 22 * IMG;
    float*       ob  = out + (size_t)b * 11 * IMG;

    float acc[4][11];
    #pragma unroll
    for (int q = 0; q < 4; q++)
        #pragma unroll
        for (int o = 0; o < 11; o++) acc[q][o] = 0.f;

    #pragma unroll 2
    for (int i = 0; i < 22; i++) {
        float v[4];
        #pragma unroll
        for (int q = 0; q < 4; q++) v[q] = inb[(size_t)i * IMG + p0 + q * 256];
        #pragma unroll
        for (int o = 0; o < 11; o++) {
            float w = s_w[o * 22 + i];
            #pragma unroll
            for (int q = 0; q < 4; q++) acc[q][o] = fmaf(v[q], w, acc[q][o]);
        }
    }
    #pragma unroll
    for (int o = 0; o < 11; o++)
        #pragma unroll
        for (int q = 0; q < 4; q++)
            ob[(size_t)o * IMG + p0 + q * 256] = acc[q][o];
}

// ---------------------------------------------------------------------------

static int smem_bytes_mma(int cinp, int coutp) {
    int kc  = cinp / 8, nbk = coutp / 8;
    int rsw = (cinp == 16) ? 20 : 28;
    return (660 * rsw + 2 * nbk * 9 * kc * 32 + 2 * coutp) * 4;
}

extern "C" void kernel_launch(void* const* d_in, const int* in_sizes, int n_in,
                              void* d_out, int out_size)
{
    const float* x   = (const float*)d_in[0];
    const float* w1  = (const float*)d_in[1];
    const float* w2  = (const float*)d_in[2];
    const float* w3  = (const float*)d_in[3];
    const float* w4  = (const float*)d_in[4];
    const float* gam = (const float*)d_in[5];
    const float* bet = (const float*)d_in[6];
    const float* mea = (const float*)d_in[7];
    const float* var = (const float*)d_in[8];
    float* out = (float*)d_out;

    float *bufA, *bufB, *bufC;
    cudaGetSymbolAddress((void**)&bufA, g_bufA);
    cudaGetSymbolAddress((void**)&bufB, g_bufB);
    cudaGetSymbolAddress((void**)&bufC, g_bufC);

    // opt-in to >48KB dynamic smem (idempotent; host-side, capture-safe)
    cudaFuncSetAttribute((const void*)conv3x3_mma<10,16,12,16>, cudaFuncAttributeMaxDynamicSharedMemorySize, smem_bytes_mma(16,16));
    cudaFuncSetAttribute((const void*)conv3x3_mma<12,16,12,16>, cudaFuncAttributeMaxDynamicSharedMemorySize, smem_bytes_mma(16,16));
    cudaFuncSetAttribute((const void*)conv3x3_mma<22,24,24,24>, cudaFuncAttributeMaxDynamicSharedMemorySize, smem_bytes_mma(24,24));
    cudaFuncSetAttribute((const void*)conv3x3_mma<24,24,24,24>, cudaFuncAttributeMaxDynamicSharedMemorySize, smem_bytes_mma(24,24));
    cudaFuncSetAttribute((const void*)conv3x3_mma<24,24,12,16>, cudaFuncAttributeMaxDynamicSharedMemorySize, smem_bytes_mma(24,16));

    const dim3 grd(2, 16, BATCH);   // 64x8 pixel tiles

    // x -> bufA channels 12..21 (skip-concat source, written once per launch)
    copy_x_kernel<<<(BATCH * 10 * IMG + 255) / 256, 256>>>(x, bufA);

    // ---- stage 1 ----  (BN offsets: 0,12,24)
    conv3x3_mma<10,16,12,16><<<grd, 256, smem_bytes_mma(16,16)>>>(x,    10, w1, 3672,    0, gam,bet,mea,var,   0, bufB, 24);
    conv3x3_mma<12,16,12,16><<<grd, 256, smem_bytes_mma(16,16)>>>(bufB, 24, w1, 3672, 1080, gam,bet,mea,var,  12, bufC, 24);
    conv3x3_mma<12,16,12,16><<<grd, 256, smem_bytes_mma(16,16)>>>(bufC, 24, w1, 3672, 2376, gam,bet,mea,var,  24, bufA, 22);
    // ---- stage 2 ----  (BN offsets: 36,60,84)
    conv3x3_mma<22,24,24,24><<<grd, 256, smem_bytes_mma(24,24)>>>(bufA, 22, w2, 12528,    0, gam,bet,mea,var,  36, bufB, 24);
    conv3x3_mma<24,24,24,24><<<grd, 256, smem_bytes_mma(24,24)>>>(bufB, 24, w2, 12528, 4752, gam,bet,mea,var,  60, bufC, 24);
    conv3x3_mma<24,24,12,16><<<grd, 256, smem_bytes_mma(24,16)>>>(bufC, 24, w2, 12528, 9936, gam,bet,mea,var,  84, bufA, 22);
    // ---- stage 3 ----  (BN offsets: 96,120,144)
    conv3x3_mma<22,24,24,24><<<grd, 256, smem_bytes_mma(24,24)>>>(bufA, 22, w3, 12528,    0, gam,bet,mea,var,  96, bufB, 24);
    conv3x3_mma<24,24,24,24><<<grd, 256, smem_bytes_mma(24,24)>>>(bufB, 24, w3, 12528, 4752, gam,bet,mea,var, 120, bufC, 24);
    conv3x3_mma<24,24,12,16><<<grd, 256, smem_bytes_mma(24,16)>>>(bufC, 24, w3, 12528, 9936, gam,bet,mea,var, 144, bufA, 22);
    // ---- stage 4: 1x1 predictor ----
    conv1x1_kernel<<<dim3(IMG / (256 * 4), BATCH), 256>>>(bufA, w4, out);
}

// round 12
// speedup vs baseline: 1.0313x; 1.0313x over previous
#include <cuda_runtime.h>
#include <cuda_bf16.h>

#define HW    128
#define IMG   (HW*HW)
#define BATCH 64

// Scratch buffers (allocation-free rule: __device__ globals)
__device__ float g_bufA[(size_t)BATCH * 22 * IMG];  // 22-ch concat; x lives in ch 12..21
__device__ float g_bufB[(size_t)BATCH * 24 * IMG];
__device__ float g_bufC[(size_t)BATCH * 24 * IMG];

// ---------------------------------------------------------------------------
// bf16 split helpers: f = hi + lo with hi = bf16_rn(f), lo = bf16_rn(f - hi).
// MMAs hi*hi, hi*lo, lo*hi (fp32 accum) recover ~1e-6 rel err.
// ---------------------------------------------------------------------------
__device__ __forceinline__ void split2(float f0, float f1, unsigned& hi, unsigned& lo) {
    __nv_bfloat16 h0 = __float2bfloat16(f0);
    __nv_bfloat16 h1 = __float2bfloat16(f1);
    __nv_bfloat16 l0 = __float2bfloat16(f0 - __bfloat162float(h0));
    __nv_bfloat16 l1 = __float2bfloat16(f1 - __bfloat162float(h1));
    hi = ((unsigned)__bfloat16_as_ushort(h1) << 16) | (unsigned)__bfloat16_as_ushort(h0);
    lo = ((unsigned)__bfloat16_as_ushort(l1) << 16) | (unsigned)__bfloat16_as_ushort(l0);
}

// mma.sync m16n8k8 bf16: C[16x8,f32] += A[16x8,bf16] * B[8x8,bf16]
__device__ __forceinline__ void mma_bf16(float c[4], unsigned a0, unsigned a1, unsigned b0) {
    asm("mma.sync.aligned.m16n8k8.row.col.f32.bf16.bf16.f32 "
        "{%0,%1,%2,%3}, {%4,%5}, {%6}, {%0,%1,%2,%3};"
        : "+f"(c[0]), "+f"(c[1]), "+f"(c[2]), "+f"(c[3])
        : "r"(a0), "r"(a1), "r"(b0));
}

// ---------------------------------------------------------------------------
// Per-sample 3x3 conv + eval-BN + ReLU via split-bf16 tensor-core MMA.
// CTA: 256 threads (8 warps), pixel tile 32x8 (halo 34x10, 340 records).
// Per k-iter: load A frags ONCE (8 LDS.32), then per n-block 2 B words +
// 6 MMAs, ALL split terms accumulating into ONE C fragment per (m,nb):
// acc regs 3x smaller than R11 -> no spills, 3-4 CTAs/SM.
// ---------------------------------------------------------------------------
template<int CIN, int CINP, int COUT, int COUTP>
__global__ __launch_bounds__(256, (COUTP == 16) ? 4 : 3)
void conv3x3_mma(const float* __restrict__ in, int in_nch,
                 const float* __restrict__ wflat, int wP, int wbase,
                 const float* __restrict__ gam, const float* __restrict__ bet,
                 const float* __restrict__ mea, const float* __restrict__ varr,
                 int bnoff,
                 float* __restrict__ out, int out_nch)
{
    constexpr int KC   = CINP / 8;           // k-chunks of 8 channels
    constexpr int NBK  = COUTP / 8;          // n-blocks of 8 outputs
    constexpr int RSW  = (CINP == 16) ? 20 : 28;  // record stride (words)
    constexpr int CHW  = CINP / 2;           // lo-section word offset
    constexpr int TXW  = 34, TYH = 10;       // halo tile (32x8 outputs)
    constexpr int NREC = TXW * TYH;          // 340 pixel records
    constexpr int BSL  = 9 * KC * 32;        // B slots per n-block

    extern __shared__ unsigned sm[];
    unsigned* s_a  = sm;                     // NREC * RSW
    unsigned* s_bh = s_a + NREC * RSW;       // NBK * BSL
    unsigned* s_bl = s_bh + NBK * BSL;       // NBK * BSL
    float*    s_sc = (float*)(s_bl + NBK * BSL);
    float*    s_bi = s_sc + COUTP;

    const int tid = threadIdx.x;
    const int bS  = blockIdx.z;
    const int gx0 = blockIdx.x * 32;
    const int gy0 = blockIdx.y * 8;

    // ---- stage A: float -> (hi,lo) bf16 pair records ----
    const float* inb = in + (size_t)bS * in_nch * IMG;
    for (int u = tid; u < (CINP / 2) * NREC; u += 256) {
        int x  = u % TXW;
        int r  = u / TXW;
        int y  = r % TYH;
        int cp = r / TYH;                    // channel pair
        int gy = gy0 - 1 + y, gx = gx0 - 1 + x;
        float f0 = 0.f, f1 = 0.f;
        bool inimg = ((unsigned)gy < HW) && ((unsigned)gx < HW);
        if (inimg && 2 * cp < CIN)     f0 = inb[(size_t)(2 * cp) * IMG + gy * HW + gx];
        if (inimg && 2 * cp + 1 < CIN) f1 = inb[(size_t)(2 * cp + 1) * IMG + gy * HW + gx];
        unsigned hi, lo; split2(f0, f1, hi, lo);
        int rec = y * TXW + x;
        s_a[rec * RSW + cp]       = hi;
        s_a[rec * RSW + CHW + cp] = lo;
    }

    // ---- prep B: gmem weights -> fragment-ordered smem (hi/lo) ----
    const float* wsrc = wflat + (size_t)bS * wP + wbase;
    for (int s = tid; s < NBK * BSL; s += 256) {
        int lane = s & 31;
        int r = s >> 5;
        int kc = r % KC;  r /= KC;
        int sh = r % 9;   r /= 9;
        int nb = r;
        int o  = nb * 8 + (lane >> 2);       // n = g
        int i0 = kc * 8 + (lane & 3) * 2;    // k = 2t, 2t+1
        float w0 = (o < COUT && i0     < CIN) ? wsrc[(o * CIN + i0    ) * 9 + sh] : 0.f;
        float w1 = (o < COUT && i0 + 1 < CIN) ? wsrc[(o * CIN + i0 + 1) * 9 + sh] : 0.f;
        unsigned hi, lo; split2(w0, w1, hi, lo);
        s_bh[s] = hi;
        s_bl[s] = lo;
    }
    if (tid < COUTP) {
        float sc = 0.f, bi = 0.f;
        if (tid < COUT) {
            int c = bnoff + tid;
            float inv = gam[c] * rsqrtf(varr[c] + 1e-5f);
            sc = inv; bi = bet[c] - mea[c] * inv;
        }
        s_sc[tid] = sc; s_bi[tid] = bi;
    }
    __syncthreads();

    const int lane = tid & 31, warp = tid >> 5;
    const int g = lane >> 2, t = lane & 3;

    const unsigned* pbh = s_bh + lane;       // + nb*BSL + q*32 (immediates)
    const unsigned* pbl = s_bl + lane;
    float* ob = out + (size_t)bS * out_nch * IMG;

    // 16 m-blocks (2 per row), one m-pair per warp
    const int mb0 = warp * 2, mb1 = warp * 2 + 1;
    const int base0 = ((mb0 >> 1) * TXW + (mb0 & 1) * 16 + g) * RSW + t;
    const int base1 = ((mb1 >> 1) * TXW + (mb1 & 1) * 16 + g) * RSW + t;

    float acc[2][NBK][4];                    // ONE fragment per (m, n-block)
    #pragma unroll
    for (int m = 0; m < 2; m++)
        #pragma unroll
        for (int nb = 0; nb < NBK; nb++)
            #pragma unroll
            for (int i = 0; i < 4; i++) acc[m][nb][i] = 0.f;

    #pragma unroll
    for (int ky = 0; ky < 3; ky++)
        #pragma unroll
        for (int kx = 0; kx < 3; kx++)
            #pragma unroll
            for (int kc = 0; kc < KC; kc++) {
                const int q   = (ky * 3 + kx) * KC + kc;
                const int off = (ky * TXW + kx) * RSW + kc * 4;
                // A fragments: loaded ONCE, reused by all n-blocks
                const unsigned ah0 = s_a[base0 + off];
                const unsigned ah1 = s_a[base0 + off + 8 * RSW];
                const unsigned al0 = s_a[base0 + off + CHW];
                const unsigned al1 = s_a[base0 + off + CHW + 8 * RSW];
                const unsigned ch0 = s_a[base1 + off];
                const unsigned ch1 = s_a[base1 + off + 8 * RSW];
                const unsigned cl0 = s_a[base1 + off + CHW];
                const unsigned cl1 = s_a[base1 + off + CHW + 8 * RSW];
                #pragma unroll
                for (int nb = 0; nb < NBK; nb++) {
                    const unsigned b_h = pbh[nb * BSL + q * 32];
                    const unsigned b_l = pbl[nb * BSL + q * 32];
                    mma_bf16(acc[0][nb], ah0, ah1, b_h);
                    mma_bf16(acc[1][nb], ch0, ch1, b_h);
                    mma_bf16(acc[0][nb], ah0, ah1, b_l);
                    mma_bf16(acc[1][nb], ch0, ch1, b_l);
                    mma_bf16(acc[0][nb], al0, al1, b_h);
                    mma_bf16(acc[1][nb], cl0, cl1, b_h);
                }
            }

    // ---- epilogue: BN (eval) + ReLU, store ----
    #pragma unroll
    for (int nb = 0; nb < NBK; nb++) {
        const int o0 = nb * 8 + 2 * t, o1 = o0 + 1;
        const float sc0 = s_sc[o0], bi0 = s_bi[o0];
        const float sc1 = s_sc[o1], bi1 = s_bi[o1];
        #pragma unroll
        for (int m = 0; m < 2; m++) {
            const int mb = warp * 2 + m;
            const int y  = gy0 + (mb >> 1);
            const int x  = gx0 + (mb & 1) * 16 + g;
            float* p = ob + (size_t)y * HW + x;
            if (o0 < COUT) {
                p[(size_t)o0 * IMG]     = fmaxf(fmaf(acc[m][nb][0], sc0, bi0), 0.f);
                p[(size_t)o0 * IMG + 8] = fmaxf(fmaf(acc[m][nb][2], sc0, bi0), 0.f);
            }
            if (o1 < COUT) {
                p[(size_t)o1 * IMG]     = fmaxf(fmaf(acc[m][nb][1], sc1, bi1), 0.f);
                p[(size_t)o1 * IMG + 8] = fmaxf(fmaf(acc[m][nb][3], sc1, bi1), 0.f);
            }
        }
    }
}

// ---------------------------------------------------------------------------
// Copy x into channels 12..21 of bufA (makes the dense-skip concat free).
// ---------------------------------------------------------------------------
__global__ void copy_x_kernel(const float* __restrict__ x, float* __restrict__ bufA)
{
    size_t idx = (size_t)blockIdx.x * blockDim.x + threadIdx.x;
    const size_t total = (size_t)BATCH * 10 * IMG;
    if (idx < total) {
        int p = (int)(idx % IMG);
        int c = (int)((idx / IMG) % 10);
        int b = (int)(idx / ((size_t)IMG * 10));
        bufA[((size_t)b * 22 + 12 + c) * IMG + p] = x[idx];
    }
}

// ---------------------------------------------------------------------------
// Final per-sample 1x1 conv: [B,22,H,W] x [B,11,22] -> [B,11,H,W]
// ---------------------------------------------------------------------------
__global__ __launch_bounds__(256)
void conv1x1_kernel(const float* __restrict__ in, const float* __restrict__ w4,
                    float* __restrict__ out)
{
    __shared__ float s_w[11 * 22];
    const int b   = blockIdx.y;
    const int tid = threadIdx.x;
    if (tid < 242) s_w[tid] = w4[b * 242 + tid];
    __syncthreads();

    const int p0 = blockIdx.x * (256 * 4) + tid;
    const float* inb = in  + (size_t)b * 22 * IMG;
    float*       ob  = out + (size_t)b * 11 * IMG;

    float acc[4][11];
    #pragma unroll
    for (int q = 0; q < 4; q++)
        #pragma unroll
        for (int o = 0; o < 11; o++) acc[q][o] = 0.f;

    #pragma unroll 2
    for (int i = 0; i < 22; i++) {
        float v[4];
        #pragma unroll
        for (int q = 0; q < 4; q++) v[q] = inb[(size_t)i * IMG + p0 + q * 256];
        #pragma unroll
        for (int o = 0; o < 11; o++) {
            float w = s_w[o * 22 + i];
            #pragma unroll
            for (int q = 0; q < 4; q++) acc[q][o] = fmaf(v[q], w, acc[q][o]);
        }
    }
    #pragma unroll
    for (int o = 0; o < 11; o++)
        #pragma unroll
        for (int q = 0; q < 4; q++)
            ob[(size_t)o * IMG + p0 + q * 256] = acc[q][o];
}

// ---------------------------------------------------------------------------

static int smem_bytes_mma(int cinp, int coutp) {
    int kc  = cinp / 8, nbk = coutp / 8;
    int rsw = (cinp == 16) ? 20 : 28;
    return (340 * rsw + 2 * nbk * 9 * kc * 32 + 2 * coutp) * 4;
}

extern "C" void kernel_launch(void* const* d_in, const int* in_sizes, int n_in,
                              void* d_out, int out_size)
{
    const float* x   = (const float*)d_in[0];
    const float* w1  = (const float*)d_in[1];
    const float* w2  = (const float*)d_in[2];
    const float* w3  = (const float*)d_in[3];
    const float* w4  = (const float*)d_in[4];
    const float* gam = (const float*)d_in[5];
    const float* bet = (const float*)d_in[6];
    const float* mea = (const float*)d_in[7];
    const float* var = (const float*)d_in[8];
    float* out = (float*)d_out;

    float *bufA, *bufB, *bufC;
    cudaGetSymbolAddress((void**)&bufA, g_bufA);
    cudaGetSymbolAddress((void**)&bufB, g_bufB);
    cudaGetSymbolAddress((void**)&bufC, g_bufC);

    // opt-in to >48KB dynamic smem (idempotent; host-side, capture-safe)
    cudaFuncSetAttribute((const void*)conv3x3_mma<10,16,12,16>, cudaFuncAttributeMaxDynamicSharedMemorySize, smem_bytes_mma(16,16));
    cudaFuncSetAttribute((const void*)conv3x3_mma<12,16,12,16>, cudaFuncAttributeMaxDynamicSharedMemorySize, smem_bytes_mma(16,16));
    cudaFuncSetAttribute((const void*)conv3x3_mma<22,24,24,24>, cudaFuncAttributeMaxDynamicSharedMemorySize, smem_bytes_mma(24,24));
    cudaFuncSetAttribute((const void*)conv3x3_mma<24,24,24,24>, cudaFuncAttributeMaxDynamicSharedMemorySize, smem_bytes_mma(24,24));
    cudaFuncSetAttribute((const void*)conv3x3_mma<24,24,12,16>, cudaFuncAttributeMaxDynamicSharedMemorySize, smem_bytes_mma(24,16));

    const dim3 grd(4, 16, BATCH);   // 32x8 pixel tiles

    // x -> bufA channels 12..21 (skip-concat source, written once per launch)
    copy_x_kernel<<<(BATCH * 10 * IMG + 255) / 256, 256>>>(x, bufA);

    // ---- stage 1 ----  (BN offsets: 0,12,24)
    conv3x3_mma<10,16,12,16><<<grd, 256, smem_bytes_mma(16,16)>>>(x,    10, w1, 3672,    0, gam,bet,mea,var,   0, bufB, 24);
    conv3x3_mma<12,16,12,16><<<grd, 256, smem_bytes_mma(16,16)>>>(bufB, 24, w1, 3672, 1080, gam,bet,mea,var,  12, bufC, 24);
    conv3x3_mma<12,16,12,16><<<grd, 256, smem_bytes_mma(16,16)>>>(bufC, 24, w1, 3672, 2376, gam,bet,mea,var,  24, bufA, 22);
    // ---- stage 2 ----  (BN offsets: 36,60,84)
    conv3x3_mma<22,24,24,24><<<grd, 256, smem_bytes_mma(24,24)>>>(bufA, 22, w2, 12528,    0, gam,bet,mea,var,  36, bufB, 24);
    conv3x3_mma<24,24,24,24><<<grd, 256, smem_bytes_mma(24,24)>>>(bufB, 24, w2, 12528, 4752, gam,bet,mea,var,  60, bufC, 24);
    conv3x3_mma<24,24,12,16><<<grd, 256, smem_bytes_mma(24,16)>>>(bufC, 24, w2, 12528, 9936, gam,bet,mea,var,  84, bufA, 22);
    // ---- stage 3 ----  (BN offsets: 96,120,144)
    conv3x3_mma<22,24,24,24><<<grd, 256, smem_bytes_mma(24,24)>>>(bufA, 22, w3, 12528,    0, gam,bet,mea,var,  96, bufB, 24);
    conv3x3_mma<24,24,24,24><<<grd, 256, smem_bytes_mma(24,24)>>>(bufB, 24, w3, 12528, 4752, gam,bet,mea,var, 120, bufC, 24);
    conv3x3_mma<24,24,12,16><<<grd, 256, smem_bytes_mma(24,16)>>>(bufC, 24, w3, 12528, 9936, gam,bet,mea,var, 144, bufA, 22);
    // ---- stage 4: 1x1 predictor ----
    conv1x1_kernel<<<dim3(IMG / (256 * 4), BATCH), 256>>>(bufA, w4, out);
}

// round 13
// speedup vs baseline: 1.0472x; 1.0155x over previous
#include <cuda_runtime.h>
#include <cuda_bf16.h>

#define HW    128
#define IMG   (HW*HW)
#define BATCH 64

// Scratch buffers (allocation-free rule: __device__ globals)
__device__ float g_bufA[(size_t)BATCH * 22 * IMG];  // 22-ch concat; x lives in ch 12..21
__device__ float g_bufB[(size_t)BATCH * 24 * IMG];
__device__ float g_bufC[(size_t)BATCH * 24 * IMG];

// ---------------------------------------------------------------------------
// bf16 split helpers: f = hi + lo with hi = bf16_rn(f), lo = bf16_rn(f - hi).
// MMAs hi*hi, hi*lo, lo*hi (fp32 accum) recover ~1e-6 rel err.
// ---------------------------------------------------------------------------
__device__ __forceinline__ void split2(float f0, float f1, unsigned& hi, unsigned& lo) {
    __nv_bfloat16 h0 = __float2bfloat16(f0);
    __nv_bfloat16 h1 = __float2bfloat16(f1);
    __nv_bfloat16 l0 = __float2bfloat16(f0 - __bfloat162float(h0));
    __nv_bfloat16 l1 = __float2bfloat16(f1 - __bfloat162float(h1));
    hi = ((unsigned)__bfloat16_as_ushort(h1) << 16) | (unsigned)__bfloat16_as_ushort(h0);
    lo = ((unsigned)__bfloat16_as_ushort(l1) << 16) | (unsigned)__bfloat16_as_ushort(l0);
}

// mma.sync m16n8k8 bf16: C[16x8,f32] += A[16x8,bf16] * B[8x8,bf16]
__device__ __forceinline__ void mma_bf16(float c[4], unsigned a0, unsigned a1, unsigned b0) {
    asm("mma.sync.aligned.m16n8k8.row.col.f32.bf16.bf16.f32 "
        "{%0,%1,%2,%3}, {%4,%5}, {%6}, {%0,%1,%2,%3};"
        : "+f"(c[0]), "+f"(c[1]), "+f"(c[2]), "+f"(c[3])
        : "r"(a0), "r"(a1), "r"(b0));
}

// ---------------------------------------------------------------------------
// Per-sample 3x3 conv + eval-BN + ReLU via split-bf16 tensor-core MMA.
// CTA: 256 threads (8 warps), pixel tile 64x8 (halo 66x10, 660 records).
// Composition of proven pieces:
//   - 64x8 tile: staging amortized over 512 px (R10)
//   - n-block-INNER: A frags loaded once per k-iter, reused by all NBK (R11)
//   - ONE fused fp32 accumulator per (m,nb): all 3 split terms accumulate
//     into the same C fragment -> 24 acc regs, no spill (R12)
//   - B hi/lo interleaved in smem -> one LDS.64 per (nb, k-iter)
// Per k-iter (NBK=3): 8 A-LDS + 3 B-LDS.64 + 18 MMA -> tensor-bound.
// ---------------------------------------------------------------------------
template<int CIN, int CINP, int COUT, int COUTP>
__global__ __launch_bounds__(256, (CINP == 16) ? 3 : 2)
void conv3x3_mma(const float* __restrict__ in, int in_nch,
                 const float* __restrict__ wflat, int wP, int wbase,
                 const float* __restrict__ gam, const float* __restrict__ bet,
                 const float* __restrict__ mea, const float* __restrict__ varr,
                 int bnoff,
                 float* __restrict__ out, int out_nch)
{
    constexpr int KC   = CINP / 8;           // k-chunks of 8 channels
    constexpr int NBK  = COUTP / 8;          // n-blocks of 8 outputs
    constexpr int RSW  = (CINP == 16) ? 20 : 28;  // record stride (words)
    constexpr int CHW  = CINP / 2;           // lo-section word offset
    constexpr int TXW  = 66, TYH = 10;       // halo tile (64x8 outputs)
    constexpr int NREC = TXW * TYH;          // 660 pixel records
    constexpr int BSL  = 9 * KC * 32;        // B slots per n-block

    extern __shared__ unsigned sm[];
    unsigned* s_a = sm;                      // NREC * RSW
    unsigned* s_b = s_a + NREC * RSW;        // NBK * BSL * 2 (hi,lo interleaved)
    float*    s_sc = (float*)(s_b + 2 * NBK * BSL);
    float*    s_bi = s_sc + COUTP;

    const int tid = threadIdx.x;
    const int bS  = blockIdx.z;
    const int gx0 = blockIdx.x * 64;
    const int gy0 = blockIdx.y * 8;

    // ---- stage A: float -> (hi,lo) bf16 pair records ----
    const float* inb = in + (size_t)bS * in_nch * IMG;
    for (int u = tid; u < (CINP / 2) * NREC; u += 256) {
        int x  = u % TXW;
        int r  = u / TXW;
        int y  = r % TYH;
        int cp = r / TYH;                    // channel pair
        int gy = gy0 - 1 + y, gx = gx0 - 1 + x;
        float f0 = 0.f, f1 = 0.f;
        bool inimg = ((unsigned)gy < HW) && ((unsigned)gx < HW);
        if (inimg && 2 * cp < CIN)     f0 = inb[(size_t)(2 * cp) * IMG + gy * HW + gx];
        if (inimg && 2 * cp + 1 < CIN) f1 = inb[(size_t)(2 * cp + 1) * IMG + gy * HW + gx];
        unsigned hi, lo; split2(f0, f1, hi, lo);
        int rec = y * TXW + x;
        s_a[rec * RSW + cp]       = hi;
        s_a[rec * RSW + CHW + cp] = lo;
    }

    // ---- prep B: gmem weights -> fragment-ordered smem, (hi,lo) interleaved ----
    const float* wsrc = wflat + (size_t)bS * wP + wbase;
    for (int s = tid; s < NBK * BSL; s += 256) {
        int lane = s & 31;
        int r = s >> 5;
        int kc = r % KC;  r /= KC;
        int sh = r % 9;   r /= 9;
        int nb = r;
        int o  = nb * 8 + (lane >> 2);       // n = g
        int i0 = kc * 8 + (lane & 3) * 2;    // k = 2t, 2t+1
        float w0 = (o < COUT && i0     < CIN) ? wsrc[(o * CIN + i0    ) * 9 + sh] : 0.f;
        float w1 = (o < COUT && i0 + 1 < CIN) ? wsrc[(o * CIN + i0 + 1) * 9 + sh] : 0.f;
        unsigned hi, lo; split2(w0, w1, hi, lo);
        s_b[2 * s]     = hi;
        s_b[2 * s + 1] = lo;
    }
    if (tid < COUTP) {
        float sc = 0.f, bi = 0.f;
        if (tid < COUT) {
            int c = bnoff + tid;
            float inv = gam[c] * rsqrtf(varr[c] + 1e-5f);
            sc = inv; bi = bet[c] - mea[c] * inv;
        }
        s_sc[tid] = sc; s_bi[tid] = bi;
    }
    __syncthreads();

    const int lane = tid & 31, warp = tid >> 5;
    const int g = lane >> 2, t = lane & 3;

    const uint2* pb = (const uint2*)s_b + lane;   // + nb*BSL + q*32 (immediates)
    float* ob = out + (size_t)bS * out_nch * IMG;

    // 32 m-blocks (16 m-pairs) / 8 warps -> 2 warp-tiles per warp
    #pragma unroll 1
    for (int jj = 0; jj < 2; jj++) {
        const int mp  = warp + 8 * jj;
        const int mb0 = mp * 2, mb1 = mp * 2 + 1;
        const int base0 = ((mb0 >> 2) * TXW + (mb0 & 3) * 16 + g) * RSW + t;
        const int base1 = ((mb1 >> 2) * TXW + (mb1 & 3) * 16 + g) * RSW + t;

        float acc[2][NBK][4];                // ONE fragment per (m, n-block)
        #pragma unroll
        for (int m = 0; m < 2; m++)
            #pragma unroll
            for (int nb = 0; nb < NBK; nb++)
                #pragma unroll
                for (int i = 0; i < 4; i++) acc[m][nb][i] = 0.f;

        #pragma unroll
        for (int ky = 0; ky < 3; ky++)
            #pragma unroll
            for (int kx = 0; kx < 3; kx++)
                #pragma unroll
                for (int kc = 0; kc < KC; kc++) {
                    const int q   = (ky * 3 + kx) * KC + kc;
                    const int off = (ky * TXW + kx) * RSW + kc * 4;
                    // A fragments: loaded ONCE, reused by all n-blocks
                    const unsigned ah0 = s_a[base0 + off];
                    const unsigned ah1 = s_a[base0 + off + 8 * RSW];
                    const unsigned al0 = s_a[base0 + off + CHW];
                    const unsigned al1 = s_a[base0 + off + CHW + 8 * RSW];
                    const unsigned ch0 = s_a[base1 + off];
                    const unsigned ch1 = s_a[base1 + off + 8 * RSW];
                    const unsigned cl0 = s_a[base1 + off + CHW];
                    const unsigned cl1 = s_a[base1 + off + CHW + 8 * RSW];
                    // B fragments: one LDS.64 per n-block (hi,lo)
                    uint2 bb[NBK];
                    #pragma unroll
                    for (int nb = 0; nb < NBK; nb++)
                        bb[nb] = pb[nb * BSL + q * 32];
                    // term-major order: each acc reused at distance 2*NBK
                    #pragma unroll
                    for (int nb = 0; nb < NBK; nb++) {
                        mma_bf16(acc[0][nb], ah0, ah1, bb[nb].x);
                        mma_bf16(acc[1][nb], ch0, ch1, bb[nb].x);
                    }
                    #pragma unroll
                    for (int nb = 0; nb < NBK; nb++) {
                        mma_bf16(acc[0][nb], ah0, ah1, bb[nb].y);
                        mma_bf16(acc[1][nb], ch0, ch1, bb[nb].y);
                    }
                    #pragma unroll
                    for (int nb = 0; nb < NBK; nb++) {
                        mma_bf16(acc[0][nb], al0, al1, bb[nb].x);
                        mma_bf16(acc[1][nb], cl0, cl1, bb[nb].x);
                    }
                }

        // ---- epilogue: BN (eval) + ReLU, store ----
        #pragma unroll
        for (int nb = 0; nb < NBK; nb++) {
            const int o0 = nb * 8 + 2 * t, o1 = o0 + 1;
            const float sc0 = s_sc[o0], bi0 = s_bi[o0];
            const float sc1 = s_sc[o1], bi1 = s_bi[o1];
            #pragma unroll
            for (int m = 0; m < 2; m++) {
                const int mb = mp * 2 + m;
                const int y  = gy0 + (mb >> 2);
                const int x  = gx0 + (mb & 3) * 16 + g;
                float* p = ob + (size_t)y * HW + x;
                if (o0 < COUT) {
                    p[(size_t)o0 * IMG]     = fmaxf(fmaf(acc[m][nb][0], sc0, bi0), 0.f);
                    p[(size_t)o0 * IMG + 8] = fmaxf(fmaf(acc[m][nb][2], sc0, bi0), 0.f);
                }
                if (o1 < COUT) {
                    p[(size_t)o1 * IMG]     = fmaxf(fmaf(acc[m][nb][1], sc1, bi1), 0.f);
                    p[(size_t)o1 * IMG + 8] = fmaxf(fmaf(acc[m][nb][3], sc1, bi1), 0.f);
                }
            }
        }
    }
}

// ---------------------------------------------------------------------------
// Copy x into channels 12..21 of bufA (makes the dense-skip concat free).
// ---------------------------------------------------------------------------
__global__ void copy_x_kernel(const float* __restrict__ x, float* __restrict__ bufA)
{
    size_t idx = (size_t)blockIdx.x * blockDim.x + threadIdx.x;
    const size_t total = (size_t)BATCH * 10 * IMG;
    if (idx < total) {
        int p = (int)(idx % IMG);
        int c = (int)((idx / IMG) % 10);
        int b = (int)(idx / ((size_t)IMG * 10));
        bufA[((size_t)b * 22 + 12 + c) * IMG + p] = x[idx];
    }
}

// ---------------------------------------------------------------------------
// Final per-sample 1x1 conv: [B,22,H,W] x [B,11,22] -> [B,11,H,W]
// ---------------------------------------------------------------------------
__global__ __launch_bounds__(256)
void conv1x1_kernel(const float* __restrict__ in, const float* __restrict__ w4,
                    float* __restrict__ out)
{
    __shared__ float s_w[11 * 22];
    const int b   = blockIdx.y;
    const int tid = threadIdx.x;
    if (tid < 242) s_w[tid] = w4[b * 242 + tid];
    __syncthreads();

    const int p0 = blockIdx.x * (256 * 4) + tid;
    const float* inb = in  + (size_t)b * 22 * IMG;
    float*       ob  = out + (size_t)b * 11 * IMG;

    float acc[4][11];
    #pragma unroll
    for (int q = 0; q < 4; q++)
        #pragma unroll
        for (int o = 0; o < 11; o++) acc[q][o] = 0.f;

    #pragma unroll 2
    for (int i = 0; i < 22; i++) {
        float v[4];
        #pragma unroll
        for (int q = 0; q < 4; q++) v[q] = inb[(size_t)i * IMG + p0 + q * 256];
        #pragma unroll
        for (int o = 0; o < 11; o++) {
            float w = s_w[o * 22 + i];
            #pragma unroll
            for (int q = 0; q < 4; q++) acc[q][o] = fmaf(v[q], w, acc[q][o]);
        }
    }
    #pragma unroll
    for (int o = 0; o < 11; o++)
        #pragma unroll
        for (int q = 0; q < 4; q++)
            ob[(size_t)o * IMG + p0 + q * 256] = acc[q][o];
}

// ---------------------------------------------------------------------------

static int smem_bytes_mma(int cinp, int coutp) {
    int kc  = cinp / 8, nbk = coutp / 8;
    int rsw = (cinp == 16) ? 20 : 28;
    return (660 * rsw + 2 * nbk * 9 * kc * 32 + 2 * coutp) * 4;
}

extern "C" void kernel_launch(void* const* d_in, const int* in_sizes, int n_in,
                              void* d_out, int out_size)
{
    const float* x   = (const float*)d_in[0];
    const float* w1  = (const float*)d_in[1];
    const float* w2  = (const float*)d_in[2];
    const float* w3  = (const float*)d_in[3];
    const float* w4  = (const float*)d_in[4];
    const float* gam = (const float*)d_in[5];
    const float* bet = (const float*)d_in[6];
    const float* mea = (const float*)d_in[7];
    const float* var = (const float*)d_in[8];
    float* out = (float*)d_out;

    float *bufA, *bufB, *bufC;
    cudaGetSymbolAddress((void**)&bufA, g_bufA);
    cudaGetSymbolAddress((void**)&bufB, g_bufB);
    cudaGetSymbolAddress((void**)&bufC, g_bufC);

    // opt-in to >48KB dynamic smem (idempotent; host-side, capture-safe)
    cudaFuncSetAttribute((const void*)conv3x3_mma<10,16,12,16>, cudaFuncAttributeMaxDynamicSharedMemorySize, smem_bytes_mma(16,16));
    cudaFuncSetAttribute((const void*)conv3x3_mma<12,16,12,16>, cudaFuncAttributeMaxDynamicSharedMemorySize, smem_bytes_mma(16,16));
    cudaFuncSetAttribute((const void*)conv3x3_mma<22,24,24,24>, cudaFuncAttributeMaxDynamicSharedMemorySize, smem_bytes_mma(24,24));
    cudaFuncSetAttribute((const void*)conv3x3_mma<24,24,24,24>, cudaFuncAttributeMaxDynamicSharedMemorySize, smem_bytes_mma(24,24));
    cudaFuncSetAttribute((const void*)conv3x3_mma<24,24,12,16>, cudaFuncAttributeMaxDynamicSharedMemorySize, smem_bytes_mma(24,16));

    const dim3 grd(2, 16, BATCH);   // 64x8 pixel tiles

    // x -> bufA channels 12..21 (skip-concat source, written once per launch)
    copy_x_kernel<<<(BATCH * 10 * IMG + 255) / 256, 256>>>(x, bufA);

    // ---- stage 1 ----  (BN offsets: 0,12,24)
    conv3x3_mma<10,16,12,16><<<grd, 256, smem_bytes_mma(16,16)>>>(x,    10, w1, 3672,    0, gam,bet,mea,var,   0, bufB, 24);
    conv3x3_mma<12,16,12,16><<<grd, 256, smem_bytes_mma(16,16)>>>(bufB, 24, w1, 3672, 1080, gam,bet,mea,var,  12, bufC, 24);
    conv3x3_mma<12,16,12,16><<<grd, 256, smem_bytes_mma(16,16)>>>(bufC, 24, w1, 3672, 2376, gam,bet,mea,var,  24, bufA, 22);
    // ---- stage 2 ----  (BN offsets: 36,60,84)
    conv3x3_mma<22,24,24,24><<<grd, 256, smem_bytes_mma(24,24)>>>(bufA, 22, w2, 12528,    0, gam,bet,mea,var,  36, bufB, 24);
    conv3x3_mma<24,24,24,24><<<grd, 256, smem_bytes_mma(24,24)>>>(bufB, 24, w2, 12528, 4752, gam,bet,mea,var,  60, bufC, 24);
    conv3x3_mma<24,24,12,16><<<grd, 256, smem_bytes_mma(24,16)>>>(bufC, 24, w2, 12528, 9936, gam,bet,mea,var,  84, bufA, 22);
    // ---- stage 3 ----  (BN offsets: 96,120,144)
    conv3x3_mma<22,24,24,24><<<grd, 256, smem_bytes_mma(24,24)>>>(bufA, 22, w3, 12528,    0, gam,bet,mea,var,  96, bufB, 24);
    conv3x3_mma<24,24,24,24><<<grd, 256, smem_bytes_mma(24,24)>>>(bufB, 24, w3, 12528, 4752, gam,bet,mea,var, 120, bufC, 24);
    conv3x3_mma<24,24,12,16><<<grd, 256, smem_bytes_mma(24,16)>>>(bufC, 24, w3, 12528, 9936, gam,bet,mea,var, 144, bufA, 22);
    // ---- stage 4: 1x1 predictor ----
    conv1x1_kernel<<<dim3(IMG / (256 * 4), BATCH), 256>>>(bufA, w4, out);
}